// round 7
// baseline (speedup 1.0000x reference)
#include <cuda_runtime.h>

// Inverse Haar (db1) 2D wavelet step, grouped transposed conv stride2/kernel2.
// Input  x: (16, 128, 128, 128) f32  -> channel pairs (2g, 2g+1)
// Filters:  (2, 2, 2) f32
// Output:   (16, 64, 256, 256) f32
//
// out[b,g,2h+i,2w+j] = x[b,2g,h,w]*f0[i,j] + x[b,2g+1,h,w]*f1[i,j]
//
// R6: R5's warp-dense layout + (a) each thread processes TWO input rows
// (h and h+64) -> 8 independent front-batched loads (MLP=8), half the warps;
// (b) streaming cache hints (__ldcs/__stcs) since every byte is touched
// exactly once -- keep the stream from thrashing L2.

#define HW_IN   (128 * 128)
#define HW_OUT  (256 * 256)
#define W_IN    128
#define W_OUT   256

__global__ __launch_bounds__(256) void iwt_kernel(
    const float* __restrict__ x,
    const float* __restrict__ f,
    float* __restrict__ out)
{
    int tid = blockIdx.x * blockDim.x + threadIdx.x;
    int i  = tid & 31;           // lane's float4-column slot
    int h  = (tid >> 5) & 63;    // input row (this thread also does h+64)
    int bg = tid >> 11;          // b*64 + g in [0,1024)

    const float f00 = __ldg(f + 0), f01 = __ldg(f + 1);
    const float f10 = __ldg(f + 2), f11 = __ldg(f + 3);
    const float g00 = __ldg(f + 4), g01 = __ldg(f + 5);
    const float g10 = __ldg(f + 6), g11 = __ldg(f + 7);

    // Row bases: channel 2g at plane 2*bg, channel 2g+1 one plane later.
    int in_base0 = 2 * bg * HW_IN + h * W_IN;            // row h
    int in_base1 = in_base0 + 64 * W_IN;                 // row h+64
    const float2* arow0 = reinterpret_cast<const float2*>(x + in_base0);
    const float2* brow0 = reinterpret_cast<const float2*>(x + in_base0 + HW_IN);
    const float2* arow1 = reinterpret_cast<const float2*>(x + in_base1);
    const float2* brow1 = reinterpret_cast<const float2*>(x + in_base1 + HW_IN);

    // 8 independent streaming loads, front-batched.
    float2 a0L = __ldcs(arow0 + i);
    float2 b0L = __ldcs(brow0 + i);
    float2 a0H = __ldcs(arow0 + 32 + i);
    float2 b0H = __ldcs(brow0 + 32 + i);
    float2 a1L = __ldcs(arow1 + i);
    float2 b1L = __ldcs(brow1 + i);
    float2 a1H = __ldcs(arow1 + 32 + i);
    float2 b1H = __ldcs(brow1 + 32 + i);

    int out_base0 = bg * HW_OUT + (h << 1) * W_OUT;          // rows 2h, 2h+1
    int out_base1 = out_base0 + 128 * W_OUT;                 // rows 2h+128, 2h+129
    float4* o00 = reinterpret_cast<float4*>(out + out_base0);
    float4* o01 = reinterpret_cast<float4*>(out + out_base0 + W_OUT);
    float4* o10 = reinterpret_cast<float4*>(out + out_base1);
    float4* o11 = reinterpret_cast<float4*>(out + out_base1 + W_OUT);

#define HAAR4(a, b, c0, c1) \
    make_float4(fmaf((b).x, (c0), (a).x * (c1 ## 0)), fmaf((b).x, (c0 ## x1), (a).x * (c1 ## 1)), \
                fmaf((b).y, (c0), (a).y * (c1 ## 0)), fmaf((b).y, (c0 ## x1), (a).y * (c1 ## 1)))

    // Row h results
    float4 r00L = make_float4(fmaf(b0L.x, g00, a0L.x * f00), fmaf(b0L.x, g01, a0L.x * f01),
                              fmaf(b0L.y, g00, a0L.y * f00), fmaf(b0L.y, g01, a0L.y * f01));
    float4 r01L = make_float4(fmaf(b0L.x, g10, a0L.x * f10), fmaf(b0L.x, g11, a0L.x * f11),
                              fmaf(b0L.y, g10, a0L.y * f10), fmaf(b0L.y, g11, a0L.y * f11));
    float4 r00H = make_float4(fmaf(b0H.x, g00, a0H.x * f00), fmaf(b0H.x, g01, a0H.x * f01),
                              fmaf(b0H.y, g00, a0H.y * f00), fmaf(b0H.y, g01, a0H.y * f01));
    float4 r01H = make_float4(fmaf(b0H.x, g10, a0H.x * f10), fmaf(b0H.x, g11, a0H.x * f11),
                              fmaf(b0H.y, g10, a0H.y * f10), fmaf(b0H.y, g11, a0H.y * f11));
    // Row h+64 results
    float4 r10L = make_float4(fmaf(b1L.x, g00, a1L.x * f00), fmaf(b1L.x, g01, a1L.x * f01),
                              fmaf(b1L.y, g00, a1L.y * f00), fmaf(b1L.y, g01, a1L.y * f01));
    float4 r11L = make_float4(fmaf(b1L.x, g10, a1L.x * f10), fmaf(b1L.x, g11, a1L.x * f11),
                              fmaf(b1L.y, g10, a1L.y * f10), fmaf(b1L.y, g11, a1L.y * f11));
    float4 r10H = make_float4(fmaf(b1H.x, g00, a1H.x * f00), fmaf(b1H.x, g01, a1H.x * f01),
                              fmaf(b1H.y, g00, a1H.y * f00), fmaf(b1H.y, g01, a1H.y * f01));
    float4 r11H = make_float4(fmaf(b1H.x, g10, a1H.x * f10), fmaf(b1H.x, g11, a1H.x * f11),
                              fmaf(b1H.y, g10, a1H.y * f10), fmaf(b1H.y, g11, a1H.y * f11));

    // Warp-dense streaming stores: each STG = 512B contiguous per warp.
    __stcs(o00 + i,      r00L);
    __stcs(o00 + 32 + i, r00H);
    __stcs(o01 + i,      r01L);
    __stcs(o01 + 32 + i, r01H);
    __stcs(o10 + i,      r10L);
    __stcs(o10 + 32 + i, r10H);
    __stcs(o11 + i,      r11L);
    __stcs(o11 + 32 + i, r11H);
#undef HAAR4
}

extern "C" void kernel_launch(void* const* d_in, const int* in_sizes, int n_in,
                              void* d_out, int out_size) {
    const float* x = (const float*)d_in[0];   // (16,128,128,128) f32
    const float* f = (const float*)d_in[1];   // (2,2,2) f32
    float* out = (float*)d_out;               // (16,64,256,256) f32

    // threads = 1024 (bg) * 64 (h) * 32 (i) = 2,097,152
    const int total = 1024 * 64 * 32;
    const int tpb = 256;
    iwt_kernel<<<total / tpb, tpb>>>(x, f, out);
}

// round 8
// speedup vs baseline: 1.0050x; 1.0050x over previous
#include <cuda_runtime.h>

// Inverse Haar (db1) 2D wavelet step, grouped transposed conv stride2/kernel2.
// Input  x: (16, 128, 128, 128) f32  -> channel pairs (2g, 2g+1)
// Filters:  (2, 2, 2) f32
// Output:   (16, 64, 256, 256) f32
//
// out[b,g,2h+i,2w+j] = x[b,2g,h,w]*f0[i,j] + x[b,2g+1,h,w]*f1[i,j]
//
// R7: R5's warp-dense geometry (the measured optimum of the load/store
// density tradeoff), block=512, streaming stores (__stcs) with default
// (caching) loads. Kernel is DRAM-streaming-bound at ~74% of HBM spec;
// traffic (134MB R + 268MB W) is mandatory and both streams are fully
// line-dense, so this is expected to sit at the machine ceiling.

#define HW_IN   (128 * 128)
#define HW_OUT  (256 * 256)
#define W_IN    128
#define W_OUT   256

__global__ __launch_bounds__(512) void iwt_kernel(
    const float* __restrict__ x,
    const float* __restrict__ f,
    float* __restrict__ out)
{
    int tid = blockIdx.x * blockDim.x + threadIdx.x;
    int i  = tid & 31;           // lane's float4-column slot
    int h  = (tid >> 5) & 127;   // input row
    int bg = tid >> 12;          // b*64 + g in [0,1024)

    const float f00 = __ldg(f + 0), f01 = __ldg(f + 1);
    const float f10 = __ldg(f + 2), f11 = __ldg(f + 3);
    const float g00 = __ldg(f + 4), g01 = __ldg(f + 5);
    const float g10 = __ldg(f + 6), g11 = __ldg(f + 7);

    // Input row bases: channel 2g at plane 2*bg, channel 2g+1 one plane later.
    int in_base = 2 * bg * HW_IN + h * W_IN;
    const float2* arow = reinterpret_cast<const float2*>(x + in_base);
    const float2* brow = reinterpret_cast<const float2*>(x + in_base + HW_IN);

    // Four independent 8B loads: input cols {2i,2i+1} and {64+2i,64+2i+1}.
    // Each load instruction: 256B contiguous per warp.
    float2 aL = __ldg(arow + i);
    float2 bL = __ldg(brow + i);
    float2 aH = __ldg(arow + 32 + i);
    float2 bH = __ldg(brow + 32 + i);

    // Output rows 2h, 2h+1; thread writes float4-cols i (low) and 32+i (high).
    int out_base = bg * HW_OUT + (h << 1) * W_OUT;
    float4* orow0 = reinterpret_cast<float4*>(out + out_base);
    float4* orow1 = reinterpret_cast<float4*>(out + out_base + W_OUT);

    float4 r0L = make_float4(fmaf(bL.x, g00, aL.x * f00), fmaf(bL.x, g01, aL.x * f01),
                             fmaf(bL.y, g00, aL.y * f00), fmaf(bL.y, g01, aL.y * f01));
    float4 r1L = make_float4(fmaf(bL.x, g10, aL.x * f10), fmaf(bL.x, g11, aL.x * f11),
                             fmaf(bL.y, g10, aL.y * f10), fmaf(bL.y, g11, aL.y * f11));
    float4 r0H = make_float4(fmaf(bH.x, g00, aH.x * f00), fmaf(bH.x, g01, aH.x * f01),
                             fmaf(bH.y, g00, aH.y * f00), fmaf(bH.y, g01, aH.y * f01));
    float4 r1H = make_float4(fmaf(bH.x, g10, aH.x * f10), fmaf(bH.x, g11, aH.x * f11),
                             fmaf(bH.y, g10, aH.y * f10), fmaf(bH.y, g11, aH.y * f11));

    // Warp-dense streaming stores: each STG = 512B contiguous per warp;
    // the 4 stores of a warp cover a contiguous 2KB output block.
    __stcs(orow0 + i,      r0L);
    __stcs(orow0 + 32 + i, r0H);
    __stcs(orow1 + i,      r1L);
    __stcs(orow1 + 32 + i, r1H);
}

extern "C" void kernel_launch(void* const* d_in, const int* in_sizes, int n_in,
                              void* d_out, int out_size) {
    const float* x = (const float*)d_in[0];   // (16,128,128,128) f32
    const float* f = (const float*)d_in[1];   // (2,2,2) f32
    float* out = (float*)d_out;               // (16,64,256,256) f32

    const int total = 16 * 64 * 128 * 32;     // 4,194,304 threads
    const int tpb = 512;
    iwt_kernel<<<total / tpb, tpb>>>(x, f, out);
}